// round 7
// baseline (speedup 1.0000x reference)
#include <cuda_runtime.h>
#include <cuda_bf16.h>
#include <cstdint>

// ---------------------------------------------------------------------------
// FourierAttention via warp-level mma.sync bf16 (sm_103 plain target).
// fp32 GEMMs emulated as bf16 split-3: C = Ahi*Bhi + Ahi*Blo + Alo*Bhi,
// realized as a single standard bf16 GEMM with a 3-phase K loop over
// PRE-SPLIT hi/lo operand arrays (split done in cheap memory-bound passes /
// epilogues, NOT in the GEMM hot loop).
// GEMM: 128x128 tile, BK=32, 3-stage cp.async pipeline, ldmatrix fragments.
// ---------------------------------------------------------------------------

#define SEQ 2048
#define DM  1024
#define NB  4
#define TOK (NB * SEQ)

// fp32 scratch
__device__ float g_Vf[(long long)TOK * DM];
__device__ float g_Sf[(long long)NB * SEQ * SEQ];
// bf16 hi/lo operand arrays
__device__ __nv_bfloat16 g_xh [(long long)TOK * DM];
__device__ __nv_bfloat16 g_xl [(long long)TOK * DM];
__device__ __nv_bfloat16 g_Wh [4][DM * DM];
__device__ __nv_bfloat16 g_Wl [4][DM * DM];
__device__ __nv_bfloat16 g_Qh [(long long)TOK * DM];
__device__ __nv_bfloat16 g_Ql [(long long)TOK * DM];
__device__ __nv_bfloat16 g_Kh [(long long)TOK * DM];
__device__ __nv_bfloat16 g_Kl [(long long)TOK * DM];
__device__ __nv_bfloat16 g_VTh[(long long)TOK * DM];
__device__ __nv_bfloat16 g_VTl[(long long)TOK * DM];
__device__ __nv_bfloat16 g_Sh [(long long)NB * SEQ * SEQ];
__device__ __nv_bfloat16 g_Sl [(long long)NB * SEQ * SEQ];
__device__ __nv_bfloat16 g_Aoh[(long long)TOK * DM];
__device__ __nv_bfloat16 g_Aol[(long long)TOK * DM];

// ---------------- helpers ----------------
__device__ __forceinline__ uint32_t smem_u32(const void* p) {
    uint32_t a;
    asm("{ .reg .u64 t; cvta.to.shared.u64 t, %1; cvt.u32.u64 %0, t; }"
        : "=r"(a) : "l"(p));
    return a;
}
__device__ __forceinline__ uint32_t pk_bf16x2(float lo, float hi) {
    uint32_t r;
    asm("cvt.rn.bf16x2.f32 %0, %1, %2;" : "=r"(r) : "f"(hi), "f"(lo));
    return r;
}
__device__ __forceinline__ void mma_bf16(float* d, const uint32_t* a,
                                         const uint32_t* b) {
    asm volatile(
        "mma.sync.aligned.m16n8k16.row.col.f32.bf16.bf16.f32 "
        "{%0,%1,%2,%3}, {%4,%5,%6,%7}, {%8,%9}, {%0,%1,%2,%3};"
        : "+f"(d[0]), "+f"(d[1]), "+f"(d[2]), "+f"(d[3])
        : "r"(a[0]), "r"(a[1]), "r"(a[2]), "r"(a[3]), "r"(b[0]), "r"(b[1]));
}
__device__ __forceinline__ void ldsm4(uint32_t* r, uint32_t addr) {
    asm volatile("ldmatrix.sync.aligned.m8n8.x4.shared.b16 {%0,%1,%2,%3}, [%4];"
                 : "=r"(r[0]), "=r"(r[1]), "=r"(r[2]), "=r"(r[3]) : "r"(addr));
}
__device__ __forceinline__ void cp16(uint32_t dst, const void* src) {
    asm volatile("cp.async.cg.shared.global [%0], [%1], 16;"
                 :: "r"(dst), "l"(src) : "memory");
}
#define CP_COMMIT() asm volatile("cp.async.commit_group;" ::: "memory")
#define CP_WAIT1()  asm volatile("cp.async.wait_group 1;" ::: "memory")

// ---------------- split-convert (fp32 -> hi/lo bf16) ----------------
__global__ void __launch_bounds__(256) convert_kernel(
    const float* __restrict__ s, __nv_bfloat16* __restrict__ h,
    __nv_bfloat16* __restrict__ l, int n4)
{
    int i = blockIdx.x * 256 + threadIdx.x;
    if (i >= n4) return;
    float4 v = ((const float4*)s)[i];
    uint32_t h0 = pk_bf16x2(v.x, v.y), h1 = pk_bf16x2(v.z, v.w);
    float r0 = v.x - __uint_as_float(h0 << 16);
    float r1 = v.y - __uint_as_float(h0 & 0xffff0000u);
    float r2 = v.z - __uint_as_float(h1 << 16);
    float r3 = v.w - __uint_as_float(h1 & 0xffff0000u);
    ((uint2*)h)[i] = make_uint2(h0, h1);
    ((uint2*)l)[i] = make_uint2(pk_bf16x2(r0, r1), pk_bf16x2(r2, r3));
}

// ---------------- GEMM ----------------
// OUT_MODE 0: fp32 C (+bias, *alpha)   OUT_MODE 1: hi/lo bf16 pair C
#define BK 32
#define LDSB 80                       // bytes per 32-bf16 row (pad: conflict-free)
#define STAGE_HALF 10240              // 128 rows * 80B
#define STAGE_BYTES 20480
#define STAGES 3
#define SMEM_BYTES (STAGES * STAGE_BYTES)   // 61440

template <int OUT_MODE, bool HAS_BIAS>
__global__ void __launch_bounds__(256, 2) mma_gemm(
    const __nv_bfloat16* __restrict__ Ah, const __nv_bfloat16* __restrict__ Al,
    const __nv_bfloat16* __restrict__ Bh, const __nv_bfloat16* __restrict__ Bl,
    const float* __restrict__ bias,
    float* __restrict__ Cf, __nv_bfloat16* __restrict__ Chi,
    __nv_bfloat16* __restrict__ Clo,
    int N, int K, float alpha,
    long long sA, long long sB, long long sC)
{
    extern __shared__ char smraw[];
    const uint32_t smb = smem_u32(smraw);
    const int tid = threadIdx.x, lane = tid & 31, wid = tid >> 5;
    const int wm = wid >> 2, wn = wid & 3;
    const long long z = blockIdx.z;
    const __nv_bfloat16* AhZ = Ah + z * sA;
    const __nv_bfloat16* AlZ = Al + z * sA;
    const __nv_bfloat16* BhZ = Bh + z * sB;
    const __nv_bfloat16* BlZ = Bl + z * sB;
    const int rowA0 = blockIdx.y * 128, colB0 = blockIdx.x * 128;
    const int nc = K >> 5, total = 3 * nc;

    float acc[4][4][4];
#pragma unroll
    for (int i = 0; i < 4; i++)
#pragma unroll
        for (int j = 0; j < 4; j++)
#pragma unroll
            for (int r = 0; r < 4; r++) acc[i][j][r] = 0.f;

    auto issue = [&](int cc) {
        int p, kr;
        if (cc < nc)            { p = 0; kr = cc; }
        else if (cc < 2 * nc)   { p = 1; kr = cc - nc; }
        else                    { p = 2; kr = cc - 2 * nc; }
        const __nv_bfloat16* As = (p == 2) ? AlZ : AhZ;
        const __nv_bfloat16* Bs = (p == 1) ? BlZ : BhZ;
        const int k0 = kr * BK;
        const uint32_t dst = smb + (cc % STAGES) * STAGE_BYTES;
#pragma unroll
        for (int i = 0; i < 2; i++) {
            const int q = tid * 2 + i;
            const int row = q >> 2, seg = q & 3;
            cp16(dst + row * LDSB + seg * 16,
                 As + (long long)(rowA0 + row) * K + k0 + seg * 8);
            cp16(dst + STAGE_HALF + row * LDSB + seg * 16,
                 Bs + (long long)(colB0 + row) * K + k0 + seg * 8);
        }
        CP_COMMIT();
    };

    issue(0);
    issue(1);

    const int rowAl = wm * 64 + (lane & 15);
    const int rowBl = wn * 32 + (lane & 15);
    const int cbb   = (lane >> 4) << 4;     // +16B for k8..15 half

    for (int cc = 0; cc < total; cc++) {
        CP_WAIT1();
        __syncthreads();
        if (cc + STAGES - 1 < total) issue(cc + STAGES - 1);
        else CP_COMMIT();               // keep group arithmetic uniform

        const uint32_t sa = smb + (cc % STAGES) * STAGE_BYTES;
        const uint32_t sb = sa + STAGE_HALF;
#pragma unroll
        for (int ks = 0; ks < 2; ks++) {
            const uint32_t cb = ks * 32 + cbb;
            uint32_t ah[4][4], bb[4][2];
#pragma unroll
            for (int mt = 0; mt < 4; mt++)
                ldsm4(ah[mt], sa + (rowAl + mt * 16) * LDSB + cb);
#pragma unroll
            for (int ntt = 0; ntt < 2; ntt++) {
                uint32_t r[4];
                ldsm4(r, sb + (rowBl + ntt * 16) * LDSB + cb);
                bb[ntt * 2][0]     = r[0];
                bb[ntt * 2 + 1][0] = r[1];
                bb[ntt * 2][1]     = r[2];
                bb[ntt * 2 + 1][1] = r[3];
            }
#pragma unroll
            for (int mt = 0; mt < 4; mt++)
#pragma unroll
                for (int nt = 0; nt < 4; nt++)
                    mma_bf16(acc[mt][nt], ah[mt], bb[nt]);
        }
        __syncthreads();
    }

    // ---------------- epilogue ----------------
    const int mbase = rowA0 + wm * 64;
    const int nbase = colB0 + wn * 32;
    const int lr = lane >> 2, lc = lane & 3;
    const long long zC = z * sC;

#pragma unroll
    for (int mt = 0; mt < 4; mt++) {
        const int m0 = mbase + mt * 16 + lr;
#pragma unroll
        for (int nt = 0; nt < 4; nt++) {
            const int n = nbase + nt * 8 + lc * 2;
            float b0 = 0.f, b1 = 0.f;
            if (HAS_BIAS) { b0 = bias[n]; b1 = bias[n + 1]; }
            float v0 = acc[mt][nt][0] * alpha + b0;
            float v1 = acc[mt][nt][1] * alpha + b1;
            float v2 = acc[mt][nt][2] * alpha + b0;
            float v3 = acc[mt][nt][3] * alpha + b1;
            if (OUT_MODE == 0) {
                *(float2*)&Cf[zC + (long long)m0 * N + n]       = make_float2(v0, v1);
                *(float2*)&Cf[zC + (long long)(m0 + 8) * N + n] = make_float2(v2, v3);
            } else {
                uint32_t h0 = pk_bf16x2(v0, v1);
                uint32_t h1 = pk_bf16x2(v2, v3);
                float r0 = v0 - __uint_as_float(h0 << 16);
                float r1 = v1 - __uint_as_float(h0 & 0xffff0000u);
                float r2 = v2 - __uint_as_float(h1 << 16);
                float r3 = v3 - __uint_as_float(h1 & 0xffff0000u);
                *(uint32_t*)&Chi[zC + (long long)m0 * N + n]       = h0;
                *(uint32_t*)&Chi[zC + (long long)(m0 + 8) * N + n] = h1;
                *(uint32_t*)&Clo[zC + (long long)m0 * N + n]       = pk_bf16x2(r0, r1);
                *(uint32_t*)&Clo[zC + (long long)(m0 + 8) * N + n] = pk_bf16x2(r2, r3);
            }
        }
    }
}

// ---------------- softmax + split (rows of 2048) ----------------
__global__ void __launch_bounds__(256) softmax_cvt(
    const float* __restrict__ S, __nv_bfloat16* __restrict__ Sh,
    __nv_bfloat16* __restrict__ Sl)
{
    const long long row = blockIdx.x;
    const float* p = S + row * (long long)SEQ;
    const int tid = threadIdx.x;

    float4 v0 = *(const float4*)&p[tid * 4];
    float4 v1 = *(const float4*)&p[1024 + tid * 4];

    float m = fmaxf(fmaxf(fmaxf(v0.x, v0.y), fmaxf(v0.z, v0.w)),
                    fmaxf(fmaxf(v1.x, v1.y), fmaxf(v1.z, v1.w)));
    __shared__ float sh[8];
#pragma unroll
    for (int o = 16; o; o >>= 1) m = fmaxf(m, __shfl_xor_sync(0xffffffffu, m, o));
    if ((tid & 31) == 0) sh[tid >> 5] = m;
    __syncthreads();
    m = sh[0];
#pragma unroll
    for (int i = 1; i < 8; i++) m = fmaxf(m, sh[i]);
    __syncthreads();

    v0.x = __expf(v0.x - m); v0.y = __expf(v0.y - m);
    v0.z = __expf(v0.z - m); v0.w = __expf(v0.w - m);
    v1.x = __expf(v1.x - m); v1.y = __expf(v1.y - m);
    v1.z = __expf(v1.z - m); v1.w = __expf(v1.w - m);

    float s = (v0.x + v0.y + v0.z + v0.w) + (v1.x + v1.y + v1.z + v1.w);
#pragma unroll
    for (int o = 16; o; o >>= 1) s += __shfl_xor_sync(0xffffffffu, s, o);
    if ((tid & 31) == 0) sh[tid >> 5] = s;
    __syncthreads();
    s = 0.f;
#pragma unroll
    for (int i = 0; i < 8; i++) s += sh[i];

    const float inv = 1.f / s;
    v0.x *= inv; v0.y *= inv; v0.z *= inv; v0.w *= inv;
    v1.x *= inv; v1.y *= inv; v1.z *= inv; v1.w *= inv;

    const long long u0 = row * (SEQ / 2) + tid * 2;           // u32 index
    const long long u1 = u0 + 512;
    uint32_t h0 = pk_bf16x2(v0.x, v0.y), h1 = pk_bf16x2(v0.z, v0.w);
    uint32_t h2 = pk_bf16x2(v1.x, v1.y), h3 = pk_bf16x2(v1.z, v1.w);
    float r0 = v0.x - __uint_as_float(h0 << 16);
    float r1 = v0.y - __uint_as_float(h0 & 0xffff0000u);
    float r2 = v0.z - __uint_as_float(h1 << 16);
    float r3 = v0.w - __uint_as_float(h1 & 0xffff0000u);
    float r4 = v1.x - __uint_as_float(h2 << 16);
    float r5 = v1.y - __uint_as_float(h2 & 0xffff0000u);
    float r6 = v1.z - __uint_as_float(h3 << 16);
    float r7 = v1.w - __uint_as_float(h3 & 0xffff0000u);
    ((uint32_t*)Sh)[u0]     = h0;
    ((uint32_t*)Sh)[u0 + 1] = h1;
    ((uint32_t*)Sh)[u1]     = h2;
    ((uint32_t*)Sh)[u1 + 1] = h3;
    ((uint32_t*)Sl)[u0]     = pk_bf16x2(r0, r1);
    ((uint32_t*)Sl)[u0 + 1] = pk_bf16x2(r2, r3);
    ((uint32_t*)Sl)[u1]     = pk_bf16x2(r4, r5);
    ((uint32_t*)Sl)[u1 + 1] = pk_bf16x2(r6, r7);
}

// ---------------- V transpose + split ([SEQ,DM] -> [DM,SEQ] hi/lo) ----------
__global__ void __launch_bounds__(256) transpose_cvt(
    const float* __restrict__ V, __nv_bfloat16* __restrict__ VTh,
    __nv_bfloat16* __restrict__ VTl)
{
    __shared__ float t[32][33];
    const long long z = blockIdx.z;
    const float* Vb = V + z * (long long)SEQ * DM;
    __nv_bfloat16* Hh = VTh + z * (long long)DM * SEQ;
    __nv_bfloat16* Hl = VTl + z * (long long)DM * SEQ;
    const int d0 = blockIdx.x * 32;
    const int s0 = blockIdx.y * 32;
    const int tx = threadIdx.x, ty = threadIdx.y;
#pragma unroll
    for (int i = 0; i < 32; i += 8)
        t[ty + i][tx] = Vb[(long long)(s0 + ty + i) * DM + d0 + tx];
    __syncthreads();
#pragma unroll
    for (int i = 0; i < 32; i += 8) {
        const float v = t[tx][ty + i];
        const __nv_bfloat16 h = __float2bfloat16(v);
        const long long idx = (long long)(d0 + ty + i) * SEQ + s0 + tx;
        Hh[idx] = h;
        Hl[idx] = __float2bfloat16(v - __bfloat162float(h));
    }
}

// ---------------- host ----------------
extern "C" void kernel_launch(void* const* d_in, const int* in_sizes, int n_in,
                              void* d_out, int out_size)
{
    const float* x  = (const float*)d_in[0];
    const float* Wq = (const float*)d_in[1];
    const float* bq = (const float*)d_in[2];
    const float* Wk = (const float*)d_in[3];
    const float* bk = (const float*)d_in[4];
    const float* Wv = (const float*)d_in[5];
    const float* bv = (const float*)d_in[6];
    const float* Wo = (const float*)d_in[7];
    const float* bo = (const float*)d_in[8];
    float* out = (float*)d_out;

    float *Vf, *Sf;
    __nv_bfloat16 *xh, *xl, *Wh, *Wl, *Qh, *Ql, *Kh, *Kl, *VTh, *VTl,
                  *Sh, *Sl, *Aoh, *Aol;
    cudaGetSymbolAddress((void**)&Vf,  g_Vf);
    cudaGetSymbolAddress((void**)&Sf,  g_Sf);
    cudaGetSymbolAddress((void**)&xh,  g_xh);
    cudaGetSymbolAddress((void**)&xl,  g_xl);
    cudaGetSymbolAddress((void**)&Wh,  g_Wh);
    cudaGetSymbolAddress((void**)&Wl,  g_Wl);
    cudaGetSymbolAddress((void**)&Qh,  g_Qh);
    cudaGetSymbolAddress((void**)&Ql,  g_Ql);
    cudaGetSymbolAddress((void**)&Kh,  g_Kh);
    cudaGetSymbolAddress((void**)&Kl,  g_Kl);
    cudaGetSymbolAddress((void**)&VTh, g_VTh);
    cudaGetSymbolAddress((void**)&VTl, g_VTl);
    cudaGetSymbolAddress((void**)&Sh,  g_Sh);
    cudaGetSymbolAddress((void**)&Sl,  g_Sl);
    cudaGetSymbolAddress((void**)&Aoh, g_Aoh);
    cudaGetSymbolAddress((void**)&Aol, g_Aol);

    cudaFuncSetAttribute(mma_gemm<0, true>,
                         cudaFuncAttributeMaxDynamicSharedMemorySize, SMEM_BYTES);
    cudaFuncSetAttribute(mma_gemm<0, false>,
                         cudaFuncAttributeMaxDynamicSharedMemorySize, SMEM_BYTES);
    cudaFuncSetAttribute(mma_gemm<1, true>,
                         cudaFuncAttributeMaxDynamicSharedMemorySize, SMEM_BYTES);
    cudaFuncSetAttribute(mma_gemm<1, false>,
                         cudaFuncAttributeMaxDynamicSharedMemorySize, SMEM_BYTES);

    // split inputs
    const int nx4 = TOK * DM / 4;         // 2097152
    const int nw4 = DM * DM / 4;          // 262144
    convert_kernel<<<(nx4 + 255) / 256, 256>>>(x, xh, xl, nx4);
    convert_kernel<<<(nw4 + 255) / 256, 256>>>(Wq, Wh + 0 * DM * DM, Wl + 0 * DM * DM, nw4);
    convert_kernel<<<(nw4 + 255) / 256, 256>>>(Wk, Wh + 1 * DM * DM, Wl + 1 * DM * DM, nw4);
    convert_kernel<<<(nw4 + 255) / 256, 256>>>(Wv, Wh + 2 * DM * DM, Wl + 2 * DM * DM, nw4);
    convert_kernel<<<(nw4 + 255) / 256, 256>>>(Wo, Wh + 3 * DM * DM, Wl + 3 * DM * DM, nw4);

    const dim3 blk(256);
    const dim3 gproj(DM / 128, TOK / 128, 1);        // (8, 64)
    const dim3 gscore(SEQ / 128, SEQ / 128, NB);     // (16, 16, 4)
    const dim3 gav(DM / 128, SEQ / 128, NB);         // (8, 16, 4)

    // Q, K projections -> hi/lo bf16 directly
    mma_gemm<1, true><<<gproj, blk, SMEM_BYTES>>>(
        xh, xl, Wh + 0 * DM * DM, Wl + 0 * DM * DM, bq,
        nullptr, Qh, Ql, DM, DM, 1.f, 0, 0, 0);
    mma_gemm<1, true><<<gproj, blk, SMEM_BYTES>>>(
        xh, xl, Wh + 1 * DM * DM, Wl + 1 * DM * DM, bk,
        nullptr, Kh, Kl, DM, DM, 1.f, 0, 0, 0);
    // V projection -> fp32 (for transpose)
    mma_gemm<0, true><<<gproj, blk, SMEM_BYTES>>>(
        xh, xl, Wh + 2 * DM * DM, Wl + 2 * DM * DM, bv,
        Vf, nullptr, nullptr, DM, DM, 1.f, 0, 0, 0);

    transpose_cvt<<<dim3(DM / 32, SEQ / 32, NB), dim3(32, 8)>>>(Vf, VTh, VTl);

    // scores -> fp32 S
    mma_gemm<0, false><<<gscore, blk, SMEM_BYTES>>>(
        Qh, Ql, Kh, Kl, nullptr, Sf, nullptr, nullptr,
        SEQ, DM, 0.125f,
        (long long)SEQ * DM, (long long)SEQ * DM, (long long)SEQ * SEQ);

    softmax_cvt<<<TOK, blk>>>(Sf, Sh, Sl);

    // attn @ V -> hi/lo bf16
    mma_gemm<1, false><<<gav, blk, SMEM_BYTES>>>(
        Sh, Sl, VTh, VTl, nullptr, nullptr, Aoh, Aol,
        DM, SEQ, 1.f,
        (long long)SEQ * SEQ, (long long)DM * SEQ, (long long)SEQ * DM);

    // output projection -> fp32 out
    mma_gemm<0, true><<<gproj, blk, SMEM_BYTES>>>(
        Aoh, Aol, Wh + 3 * DM * DM, Wl + 3 * DM * DM, bo,
        out, nullptr, nullptr, DM, DM, 1.f, 0, 0, 0);
}

// round 8
// speedup vs baseline: 1.4715x; 1.4715x over previous
#include <cuda_runtime.h>
#include <cuda_fp16.h>
#include <cstdint>

// ---------------------------------------------------------------------------
// FourierAttention via warp-level mma.sync fp16 (sm_103 plain target;
// tcgen05 unavailable in this toolchain).
// fp32 GEMMs emulated as fp16 split-2: A = Ah + Al (fp16 pair, ~22-bit),
// B rounded to fp16 once:  C = Ah*Bh + Al*Bh  -> 2-phase K loop.
// Legacy HMMA on sm_103 measures ~512 MAC/cyc/SM, so instruction count is
// the binding constraint; 2 phases = 2/3 the instructions of split-3.
// GEMM: 128x128 tile, BK=32, 3-stage cp.async pipeline, ldmatrix fragments.
// ---------------------------------------------------------------------------

#define SEQ 2048
#define DM  1024
#define NB  4
#define TOK (NB * SEQ)

// fp32 scratch
__device__ float g_Vf[(long long)TOK * DM];
__device__ float g_Sf[(long long)NB * SEQ * SEQ];
// fp16 operand arrays (A-side: hi+lo; B-side: rounded hi only)
__device__ __half g_xh [(long long)TOK * DM];
__device__ __half g_xl [(long long)TOK * DM];
__device__ __half g_Wh [4][DM * DM];
__device__ __half g_Qh [(long long)TOK * DM];
__device__ __half g_Ql [(long long)TOK * DM];
__device__ __half g_Kh [(long long)TOK * DM];
__device__ __half g_VTh[(long long)TOK * DM];
__device__ __half g_Sh [(long long)NB * SEQ * SEQ];
__device__ __half g_Sl [(long long)NB * SEQ * SEQ];
__device__ __half g_Aoh[(long long)TOK * DM];
__device__ __half g_Aol[(long long)TOK * DM];

// ---------------- helpers ----------------
__device__ __forceinline__ uint32_t smem_u32(const void* p) {
    uint32_t a;
    asm("{ .reg .u64 t; cvta.to.shared.u64 t, %1; cvt.u32.u64 %0, t; }"
        : "=r"(a) : "l"(p));
    return a;
}
// pack two fp32 -> fp16x2 (lo in low half, hi in high half)
__device__ __forceinline__ uint32_t pk_f16x2(float lo, float hi) {
    uint32_t r;
    asm("cvt.rn.f16x2.f32 %0, %1, %2;" : "=r"(r) : "f"(hi), "f"(lo));
    return r;
}
// residuals of a packed pair vs the original floats
__device__ __forceinline__ float2 resid2(float a, float b, uint32_t packed) {
    __half2 h = *reinterpret_cast<__half2*>(&packed);
    return make_float2(a - __low2float(h), b - __high2float(h));
}
__device__ __forceinline__ void mma_fp16(float* d, const uint32_t* a,
                                         const uint32_t* b) {
    asm volatile(
        "mma.sync.aligned.m16n8k16.row.col.f32.f16.f16.f32 "
        "{%0,%1,%2,%3}, {%4,%5,%6,%7}, {%8,%9}, {%0,%1,%2,%3};"
        : "+f"(d[0]), "+f"(d[1]), "+f"(d[2]), "+f"(d[3])
        : "r"(a[0]), "r"(a[1]), "r"(a[2]), "r"(a[3]), "r"(b[0]), "r"(b[1]));
}
__device__ __forceinline__ void ldsm4(uint32_t* r, uint32_t addr) {
    asm volatile("ldmatrix.sync.aligned.m8n8.x4.shared.b16 {%0,%1,%2,%3}, [%4];"
                 : "=r"(r[0]), "=r"(r[1]), "=r"(r[2]), "=r"(r[3]) : "r"(addr));
}
__device__ __forceinline__ void cp16(uint32_t dst, const void* src) {
    asm volatile("cp.async.cg.shared.global [%0], [%1], 16;"
                 :: "r"(dst), "l"(src) : "memory");
}
#define CP_COMMIT() asm volatile("cp.async.commit_group;" ::: "memory")
#define CP_WAIT1()  asm volatile("cp.async.wait_group 1;" ::: "memory")

// ---------------- converts ----------------
// split: fp32 -> fp16 hi + fp16 lo
__global__ void __launch_bounds__(256) convert_split(
    const float* __restrict__ s, __half* __restrict__ h,
    __half* __restrict__ l, int n4)
{
    int i = blockIdx.x * 256 + threadIdx.x;
    if (i >= n4) return;
    float4 v = ((const float4*)s)[i];
    uint32_t h0 = pk_f16x2(v.x, v.y), h1 = pk_f16x2(v.z, v.w);
    float2 r0 = resid2(v.x, v.y, h0);
    float2 r1 = resid2(v.z, v.w, h1);
    ((uint2*)h)[i] = make_uint2(h0, h1);
    ((uint2*)l)[i] = make_uint2(pk_f16x2(r0.x, r0.y), pk_f16x2(r1.x, r1.y));
}
// round: fp32 -> fp16
__global__ void __launch_bounds__(256) convert_round(
    const float* __restrict__ s, __half* __restrict__ h, int n4)
{
    int i = blockIdx.x * 256 + threadIdx.x;
    if (i >= n4) return;
    float4 v = ((const float4*)s)[i];
    ((uint2*)h)[i] = make_uint2(pk_f16x2(v.x, v.y), pk_f16x2(v.z, v.w));
}

// ---------------- GEMM ----------------
// OUT_MODE 0: fp32 C (+bias, *alpha)
// OUT_MODE 1: fp16 hi/lo pair C
// OUT_MODE 2: fp16 rounded C only
#define BK 32
#define LDSB 80                       // bytes per 32-fp16 row (pad: conflict-free)
#define STAGE_HALF 10240              // 128 rows * 80B
#define STAGE_BYTES 20480
#define STAGES 3
#define SMEM_BYTES (STAGES * STAGE_BYTES)   // 61440

template <int OUT_MODE, bool HAS_BIAS>
__global__ void __launch_bounds__(256, 2) mma_gemm(
    const __half* __restrict__ Ah, const __half* __restrict__ Al,
    const __half* __restrict__ Bh,
    const float* __restrict__ bias,
    float* __restrict__ Cf, __half* __restrict__ Chi, __half* __restrict__ Clo,
    int N, int K, float alpha,
    long long sA, long long sB, long long sC)
{
    extern __shared__ char smraw[];
    const uint32_t smb = smem_u32(smraw);
    const int tid = threadIdx.x, lane = tid & 31, wid = tid >> 5;
    const int wm = wid >> 2, wn = wid & 3;
    const long long z = blockIdx.z;
    const __half* AhZ = Ah + z * sA;
    const __half* AlZ = Al + z * sA;
    const __half* BhZ = Bh + z * sB;
    const int rowA0 = blockIdx.y * 128, colB0 = blockIdx.x * 128;
    const int nc = K >> 5, total = 2 * nc;   // 2 phases: Ah*Bh, Al*Bh

    float acc[4][4][4];
#pragma unroll
    for (int i = 0; i < 4; i++)
#pragma unroll
        for (int j = 0; j < 4; j++)
#pragma unroll
            for (int r = 0; r < 4; r++) acc[i][j][r] = 0.f;

    auto issue = [&](int cc) {
        const int kr = (cc < nc) ? cc : cc - nc;
        const __half* As = (cc < nc) ? AhZ : AlZ;
        const int k0 = kr * BK;
        const uint32_t dst = smb + (cc % STAGES) * STAGE_BYTES;
#pragma unroll
        for (int i = 0; i < 2; i++) {
            const int q = tid * 2 + i;
            const int row = q >> 2, seg = q & 3;
            cp16(dst + row * LDSB + seg * 16,
                 As + (long long)(rowA0 + row) * K + k0 + seg * 8);
            cp16(dst + STAGE_HALF + row * LDSB + seg * 16,
                 BhZ + (long long)(colB0 + row) * K + k0 + seg * 8);
        }
        CP_COMMIT();
    };

    issue(0);
    issue(1);

    const int rowAl = wm * 64 + (lane & 15);
    const int rowBl = wn * 32 + (lane & 15);
    const int cbb   = (lane >> 4) << 4;     // +16B for k8..15 half

    for (int cc = 0; cc < total; cc++) {
        CP_WAIT1();
        __syncthreads();
        if (cc + STAGES - 1 < total) issue(cc + STAGES - 1);
        else CP_COMMIT();               // keep group arithmetic uniform

        const uint32_t sa = smb + (cc % STAGES) * STAGE_BYTES;
        const uint32_t sb = sa + STAGE_HALF;
#pragma unroll
        for (int ks = 0; ks < 2; ks++) {
            const uint32_t cb = ks * 32 + cbb;
            uint32_t ah[4][4], bb[4][2];
#pragma unroll
            for (int mt = 0; mt < 4; mt++)
                ldsm4(ah[mt], sa + (rowAl + mt * 16) * LDSB + cb);
#pragma unroll
            for (int ntt = 0; ntt < 2; ntt++) {
                uint32_t r[4];
                ldsm4(r, sb + (rowBl + ntt * 16) * LDSB + cb);
                bb[ntt * 2][0]     = r[0];
                bb[ntt * 2 + 1][0] = r[1];
                bb[ntt * 2][1]     = r[2];
                bb[ntt * 2 + 1][1] = r[3];
            }
#pragma unroll
            for (int mt = 0; mt < 4; mt++)
#pragma unroll
                for (int nt = 0; nt < 4; nt++)
                    mma_fp16(acc[mt][nt], ah[mt], bb[nt]);
        }
        __syncthreads();
    }

    // ---------------- epilogue ----------------
    const int mbase = rowA0 + wm * 64;
    const int nbase = colB0 + wn * 32;
    const int lr = lane >> 2, lc = lane & 3;
    const long long zC = z * sC;

#pragma unroll
    for (int mt = 0; mt < 4; mt++) {
        const int m0 = mbase + mt * 16 + lr;
#pragma unroll
        for (int nt = 0; nt < 4; nt++) {
            const int n = nbase + nt * 8 + lc * 2;
            float b0 = 0.f, b1 = 0.f;
            if (HAS_BIAS) { b0 = bias[n]; b1 = bias[n + 1]; }
            float v0 = acc[mt][nt][0] * alpha + b0;
            float v1 = acc[mt][nt][1] * alpha + b1;
            float v2 = acc[mt][nt][2] * alpha + b0;
            float v3 = acc[mt][nt][3] * alpha + b1;
            if (OUT_MODE == 0) {
                *(float2*)&Cf[zC + (long long)m0 * N + n]       = make_float2(v0, v1);
                *(float2*)&Cf[zC + (long long)(m0 + 8) * N + n] = make_float2(v2, v3);
            } else if (OUT_MODE == 2) {
                *(uint32_t*)&Chi[zC + (long long)m0 * N + n]       = pk_f16x2(v0, v1);
                *(uint32_t*)&Chi[zC + (long long)(m0 + 8) * N + n] = pk_f16x2(v2, v3);
            } else {
                uint32_t h0 = pk_f16x2(v0, v1);
                uint32_t h1 = pk_f16x2(v2, v3);
                float2 r0 = resid2(v0, v1, h0);
                float2 r1 = resid2(v2, v3, h1);
                *(uint32_t*)&Chi[zC + (long long)m0 * N + n]       = h0;
                *(uint32_t*)&Chi[zC + (long long)(m0 + 8) * N + n] = h1;
                *(uint32_t*)&Clo[zC + (long long)m0 * N + n]       = pk_f16x2(r0.x, r0.y);
                *(uint32_t*)&Clo[zC + (long long)(m0 + 8) * N + n] = pk_f16x2(r1.x, r1.y);
            }
        }
    }
}

// ---------------- softmax + split (rows of 2048) ----------------
__global__ void __launch_bounds__(256) softmax_cvt(
    const float* __restrict__ S, __half* __restrict__ Sh,
    __half* __restrict__ Sl)
{
    const long long row = blockIdx.x;
    const float* p = S + row * (long long)SEQ;
    const int tid = threadIdx.x;

    float4 v0 = *(const float4*)&p[tid * 4];
    float4 v1 = *(const float4*)&p[1024 + tid * 4];

    float m = fmaxf(fmaxf(fmaxf(v0.x, v0.y), fmaxf(v0.z, v0.w)),
                    fmaxf(fmaxf(v1.x, v1.y), fmaxf(v1.z, v1.w)));
    __shared__ float sh[8];
#pragma unroll
    for (int o = 16; o; o >>= 1) m = fmaxf(m, __shfl_xor_sync(0xffffffffu, m, o));
    if ((tid & 31) == 0) sh[tid >> 5] = m;
    __syncthreads();
    m = sh[0];
#pragma unroll
    for (int i = 1; i < 8; i++) m = fmaxf(m, sh[i]);
    __syncthreads();

    v0.x = __expf(v0.x - m); v0.y = __expf(v0.y - m);
    v0.z = __expf(v0.z - m); v0.w = __expf(v0.w - m);
    v1.x = __expf(v1.x - m); v1.y = __expf(v1.y - m);
    v1.z = __expf(v1.z - m); v1.w = __expf(v1.w - m);

    float s = (v0.x + v0.y + v0.z + v0.w) + (v1.x + v1.y + v1.z + v1.w);
#pragma unroll
    for (int o = 16; o; o >>= 1) s += __shfl_xor_sync(0xffffffffu, s, o);
    if ((tid & 31) == 0) sh[tid >> 5] = s;
    __syncthreads();
    s = 0.f;
#pragma unroll
    for (int i = 0; i < 8; i++) s += sh[i];

    const float inv = 1.f / s;
    v0.x *= inv; v0.y *= inv; v0.z *= inv; v0.w *= inv;
    v1.x *= inv; v1.y *= inv; v1.z *= inv; v1.w *= inv;

    const long long u0 = row * (SEQ / 2) + tid * 2;           // u32 index
    const long long u1 = u0 + 512;
    uint32_t h0 = pk_f16x2(v0.x, v0.y), h1 = pk_f16x2(v0.z, v0.w);
    uint32_t h2 = pk_f16x2(v1.x, v1.y), h3 = pk_f16x2(v1.z, v1.w);
    float2 r0 = resid2(v0.x, v0.y, h0);
    float2 r1 = resid2(v0.z, v0.w, h1);
    float2 r2 = resid2(v1.x, v1.y, h2);
    float2 r3 = resid2(v1.z, v1.w, h3);
    ((uint32_t*)Sh)[u0]     = h0;
    ((uint32_t*)Sh)[u0 + 1] = h1;
    ((uint32_t*)Sh)[u1]     = h2;
    ((uint32_t*)Sh)[u1 + 1] = h3;
    ((uint32_t*)Sl)[u0]     = pk_f16x2(r0.x, r0.y);
    ((uint32_t*)Sl)[u0 + 1] = pk_f16x2(r1.x, r1.y);
    ((uint32_t*)Sl)[u1]     = pk_f16x2(r2.x, r2.y);
    ((uint32_t*)Sl)[u1 + 1] = pk_f16x2(r3.x, r3.y);
}

// ---------------- V transpose + round ([SEQ,DM] -> [DM,SEQ] fp16) ----------
__global__ void __launch_bounds__(256) transpose_cvt(
    const float* __restrict__ V, __half* __restrict__ VTh)
{
    __shared__ float t[32][33];
    const long long z = blockIdx.z;
    const float* Vb = V + z * (long long)SEQ * DM;
    __half* Hh = VTh + z * (long long)DM * SEQ;
    const int d0 = blockIdx.x * 32;
    const int s0 = blockIdx.y * 32;
    const int tx = threadIdx.x, ty = threadIdx.y;
#pragma unroll
    for (int i = 0; i < 32; i += 8)
        t[ty + i][tx] = Vb[(long long)(s0 + ty + i) * DM + d0 + tx];
    __syncthreads();
#pragma unroll
    for (int i = 0; i < 32; i += 8) {
        const float v = t[tx][ty + i];
        Hh[(long long)(d0 + ty + i) * SEQ + s0 + tx] = __float2half_rn(v);
    }
}

// ---------------- host ----------------
extern "C" void kernel_launch(void* const* d_in, const int* in_sizes, int n_in,
                              void* d_out, int out_size)
{
    const float* x  = (const float*)d_in[0];
    const float* Wq = (const float*)d_in[1];
    const float* bq = (const float*)d_in[2];
    const float* Wk = (const float*)d_in[3];
    const float* bk = (const float*)d_in[4];
    const float* Wv = (const float*)d_in[5];
    const float* bv = (const float*)d_in[6];
    const float* Wo = (const float*)d_in[7];
    const float* bo = (const float*)d_in[8];
    float* out = (float*)d_out;

    float *Vf, *Sf;
    __half *xh, *xl, *Wh, *Qh, *Ql, *Kh, *VTh, *Sh, *Sl, *Aoh, *Aol;
    cudaGetSymbolAddress((void**)&Vf,  g_Vf);
    cudaGetSymbolAddress((void**)&Sf,  g_Sf);
    cudaGetSymbolAddress((void**)&xh,  g_xh);
    cudaGetSymbolAddress((void**)&xl,  g_xl);
    cudaGetSymbolAddress((void**)&Wh,  g_Wh);
    cudaGetSymbolAddress((void**)&Qh,  g_Qh);
    cudaGetSymbolAddress((void**)&Ql,  g_Ql);
    cudaGetSymbolAddress((void**)&Kh,  g_Kh);
    cudaGetSymbolAddress((void**)&VTh, g_VTh);
    cudaGetSymbolAddress((void**)&Sh,  g_Sh);
    cudaGetSymbolAddress((void**)&Sl,  g_Sl);
    cudaGetSymbolAddress((void**)&Aoh, g_Aoh);
    cudaGetSymbolAddress((void**)&Aol, g_Aol);

    cudaFuncSetAttribute(mma_gemm<0, true>,
                         cudaFuncAttributeMaxDynamicSharedMemorySize, SMEM_BYTES);
    cudaFuncSetAttribute(mma_gemm<0, false>,
                         cudaFuncAttributeMaxDynamicSharedMemorySize, SMEM_BYTES);
    cudaFuncSetAttribute(mma_gemm<1, true>,
                         cudaFuncAttributeMaxDynamicSharedMemorySize, SMEM_BYTES);
    cudaFuncSetAttribute(mma_gemm<1, false>,
                         cudaFuncAttributeMaxDynamicSharedMemorySize, SMEM_BYTES);
    cudaFuncSetAttribute(mma_gemm<2, true>,
                         cudaFuncAttributeMaxDynamicSharedMemorySize, SMEM_BYTES);
    cudaFuncSetAttribute(mma_gemm<2, false>,
                         cudaFuncAttributeMaxDynamicSharedMemorySize, SMEM_BYTES);

    // split/round inputs
    const int nx4 = TOK * DM / 4;         // 2097152
    const int nw4 = DM * DM / 4;          // 262144
    convert_split<<<(nx4 + 255) / 256, 256>>>(x, xh, xl, nx4);
    convert_round<<<(nw4 + 255) / 256, 256>>>(Wq, Wh + 0 * DM * DM, nw4);
    convert_round<<<(nw4 + 255) / 256, 256>>>(Wk, Wh + 1 * DM * DM, nw4);
    convert_round<<<(nw4 + 255) / 256, 256>>>(Wv, Wh + 2 * DM * DM, nw4);
    convert_round<<<(nw4 + 255) / 256, 256>>>(Wo, Wh + 3 * DM * DM, nw4);

    const dim3 blk(256);
    const dim3 gproj(DM / 128, TOK / 128, 1);        // (8, 64)
    const dim3 gscore(SEQ / 128, SEQ / 128, NB);     // (16, 16, 4)
    const dim3 gav(DM / 128, SEQ / 128, NB);         // (8, 16, 4)

    // Q projection -> fp16 hi/lo (A-side of scores)
    mma_gemm<1, true><<<gproj, blk, SMEM_BYTES>>>(
        xh, xl, Wh + 0 * DM * DM, bq, nullptr, Qh, Ql, DM, DM, 1.f, 0, 0, 0);
    // K projection -> fp16 rounded (B-side of scores)
    mma_gemm<2, true><<<gproj, blk, SMEM_BYTES>>>(
        xh, xl, Wh + 1 * DM * DM, bk, nullptr, Kh, nullptr, DM, DM, 1.f, 0, 0, 0);
    // V projection -> fp32 (for transpose)
    mma_gemm<0, true><<<gproj, blk, SMEM_BYTES>>>(
        xh, xl, Wh + 2 * DM * DM, bv, Vf, nullptr, nullptr, DM, DM, 1.f, 0, 0, 0);

    transpose_cvt<<<dim3(DM / 32, SEQ / 32, NB), dim3(32, 8)>>>(Vf, VTh);

    // scores -> fp32 S (alpha = 0.125)
    mma_gemm<0, false><<<gscore, blk, SMEM_BYTES>>>(
        Qh, Ql, Kh, nullptr, Sf, nullptr, nullptr,
        SEQ, DM, 0.125f,
        (long long)SEQ * DM, (long long)SEQ * DM, (long long)SEQ * SEQ);

    softmax_cvt<<<TOK, blk>>>(Sf, Sh, Sl);

    // attn @ V -> fp16 hi/lo (A-side of out-proj)
    mma_gemm<1, false><<<gav, blk, SMEM_BYTES>>>(
        Sh, Sl, VTh, nullptr, nullptr, Aoh, Aol,
        DM, SEQ, 1.f,
        (long long)SEQ * SEQ, (long long)DM * SEQ, (long long)SEQ * DM);

    // output projection -> fp32 out
    mma_gemm<0, true><<<gproj, blk, SMEM_BYTES>>>(
        Aoh, Aol, Wh + 3 * DM * DM, bo, out, nullptr, nullptr, DM, DM, 1.f, 0, 0, 0);
}

// round 17
// speedup vs baseline: 1.8997x; 1.2910x over previous
#include <cuda_runtime.h>
#include <cuda_fp16.h>
#include <cstdint>

// ---------------------------------------------------------------------------
// FourierAttention via warp-level mma.sync fp16 (sm_103 plain target).
// Legacy HMMA floor ~512 MAC/cyc/SM => MMA instruction count is the lever.
// Mixed-precision schedule:
//   Q/K/V proj : A = x split-2 (xh+xl), B = W rounded     -> 2-phase
//   scores     : A = Q rounded, B = K rounded             -> 1-phase
//   attn @ V   : A = S rounded, B = VT rounded            -> 1-phase
//   out proj   : A = Ao split-2, B = Wo rounded           -> 2-phase
// GEMM: 128x128 tile, BK=32, 3-stage cp.async pipeline, ldmatrix fragments.
// ---------------------------------------------------------------------------

#define SEQ 2048
#define DM  1024
#define NB  4
#define TOK (NB * SEQ)

// fp32 scratch
__device__ float g_Sf[(long long)NB * SEQ * SEQ];
// fp16 operand arrays
__device__ __half g_xh [(long long)TOK * DM];
__device__ __half g_xl [(long long)TOK * DM];
__device__ __half g_Wh [4][DM * DM];
__device__ __half g_Qh [(long long)TOK * DM];
__device__ __half g_Kh [(long long)TOK * DM];
__device__ __half g_Vh [(long long)TOK * DM];
__device__ __half g_VTh[(long long)TOK * DM];
__device__ __half g_Sh [(long long)NB * SEQ * SEQ];
__device__ __half g_Aoh[(long long)TOK * DM];
__device__ __half g_Aol[(long long)TOK * DM];

// ---------------- helpers ----------------
__device__ __forceinline__ uint32_t smem_u32(const void* p) {
    uint32_t a;
    asm("{ .reg .u64 t; cvta.to.shared.u64 t, %1; cvt.u32.u64 %0, t; }"
        : "=r"(a) : "l"(p));
    return a;
}
__device__ __forceinline__ uint32_t pk_f16x2(float lo, float hi) {
    uint32_t r;
    asm("cvt.rn.f16x2.f32 %0, %1, %2;" : "=r"(r) : "f"(hi), "f"(lo));
    return r;
}
__device__ __forceinline__ float2 resid2(float a, float b, uint32_t packed) {
    __half2 h = *reinterpret_cast<__half2*>(&packed);
    return make_float2(a - __low2float(h), b - __high2float(h));
}
__device__ __forceinline__ void mma_fp16(float* d, const uint32_t* a,
                                         const uint32_t* b) {
    asm volatile(
        "mma.sync.aligned.m16n8k16.row.col.f32.f16.f16.f32 "
        "{%0,%1,%2,%3}, {%4,%5,%6,%7}, {%8,%9}, {%0,%1,%2,%3};"
        : "+f"(d[0]), "+f"(d[1]), "+f"(d[2]), "+f"(d[3])
        : "r"(a[0]), "r"(a[1]), "r"(a[2]), "r"(a[3]), "r"(b[0]), "r"(b[1]));
}
__device__ __forceinline__ void ldsm4(uint32_t* r, uint32_t addr) {
    asm volatile("ldmatrix.sync.aligned.m8n8.x4.shared.b16 {%0,%1,%2,%3}, [%4];"
                 : "=r"(r[0]), "=r"(r[1]), "=r"(r[2]), "=r"(r[3]) : "r"(addr));
}
__device__ __forceinline__ void cp16(uint32_t dst, const void* src) {
    asm volatile("cp.async.cg.shared.global [%0], [%1], 16;"
                 :: "r"(dst), "l"(src) : "memory");
}
#define CP_COMMIT() asm volatile("cp.async.commit_group;" ::: "memory")
#define CP_WAIT1()  asm volatile("cp.async.wait_group 1;" ::: "memory")

// ---------------- converts ----------------
__global__ void __launch_bounds__(256) convert_split(
    const float* __restrict__ s, __half* __restrict__ h,
    __half* __restrict__ l, int n4)
{
    int i = blockIdx.x * 256 + threadIdx.x;
    if (i >= n4) return;
    float4 v = ((const float4*)s)[i];
    uint32_t h0 = pk_f16x2(v.x, v.y), h1 = pk_f16x2(v.z, v.w);
    float2 r0 = resid2(v.x, v.y, h0);
    float2 r1 = resid2(v.z, v.w, h1);
    ((uint2*)h)[i] = make_uint2(h0, h1);
    ((uint2*)l)[i] = make_uint2(pk_f16x2(r0.x, r0.y), pk_f16x2(r1.x, r1.y));
}
__global__ void __launch_bounds__(256) convert_round(
    const float* __restrict__ s, __half* __restrict__ h, int n4)
{
    int i = blockIdx.x * 256 + threadIdx.x;
    if (i >= n4) return;
    float4 v = ((const float4*)s)[i];
    ((uint2*)h)[i] = make_uint2(pk_f16x2(v.x, v.y), pk_f16x2(v.z, v.w));
}

// ---------------- GEMM ----------------
// NPH: 1 = A rounded only, 2 = A hi+lo phases
// OUT_MODE 0: fp32 C (+bias,*alpha)  1: fp16 hi/lo pair  2: fp16 rounded
#define BK 32
#define LDSB 80
#define STAGE_HALF 10240
#define STAGE_BYTES 20480
#define STAGES 3
#define SMEM_BYTES (STAGES * STAGE_BYTES)   // 61440

template <int NPH, int OUT_MODE, bool HAS_BIAS>
__global__ void __launch_bounds__(256, 2) mma_gemm(
    const __half* __restrict__ Ah, const __half* __restrict__ Al,
    const __half* __restrict__ Bh,
    const float* __restrict__ bias,
    float* __restrict__ Cf, __half* __restrict__ Chi, __half* __restrict__ Clo,
    int N, int K, float alpha,
    long long sA, long long sB, long long sC)
{
    extern __shared__ char smraw[];
    const uint32_t smb = smem_u32(smraw);
    const int tid = threadIdx.x, lane = tid & 31, wid = tid >> 5;
    const int wm = wid >> 2, wn = wid & 3;
    const long long z = blockIdx.z;
    const __half* AhZ = Ah + z * sA;
    const __half* AlZ = (NPH == 2) ? Al + z * sA : nullptr;
    const __half* BhZ = Bh + z * sB;
    const int rowA0 = blockIdx.y * 128, colB0 = blockIdx.x * 128;
    const int nc = K >> 5, total = NPH * nc;

    float acc[4][4][4];
#pragma unroll
    for (int i = 0; i < 4; i++)
#pragma unroll
        for (int j = 0; j < 4; j++)
#pragma unroll
            for (int r = 0; r < 4; r++) acc[i][j][r] = 0.f;

    auto issue = [&](int cc) {
        const int kr = (cc < nc) ? cc : cc - nc;
        const __half* As = (NPH == 2 && cc >= nc) ? AlZ : AhZ;
        const int k0 = kr * BK;
        const uint32_t dst = smb + (cc % STAGES) * STAGE_BYTES;
#pragma unroll
        for (int i = 0; i < 2; i++) {
            const int q = tid * 2 + i;
            const int row = q >> 2, seg = q & 3;
            cp16(dst + row * LDSB + seg * 16,
                 As + (long long)(rowA0 + row) * K + k0 + seg * 8);
            cp16(dst + STAGE_HALF + row * LDSB + seg * 16,
                 BhZ + (long long)(colB0 + row) * K + k0 + seg * 8);
        }
        CP_COMMIT();
    };

    issue(0);
    issue(1);

    const int rowAl = wm * 64 + (lane & 15);
    const int rowBl = wn * 32 + (lane & 15);
    const int cbb   = (lane >> 4) << 4;

    for (int cc = 0; cc < total; cc++) {
        CP_WAIT1();
        __syncthreads();
        if (cc + STAGES - 1 < total) issue(cc + STAGES - 1);
        else CP_COMMIT();

        const uint32_t sa = smb + (cc % STAGES) * STAGE_BYTES;
        const uint32_t sb = sa + STAGE_HALF;
#pragma unroll
        for (int ks = 0; ks < 2; ks++) {
            const uint32_t cb = ks * 32 + cbb;
            uint32_t ah[4][4], bb[4][2];
#pragma unroll
            for (int mt = 0; mt < 4; mt++)
                ldsm4(ah[mt], sa + (rowAl + mt * 16) * LDSB + cb);
#pragma unroll
            for (int ntt = 0; ntt < 2; ntt++) {
                uint32_t r[4];
                ldsm4(r, sb + (rowBl + ntt * 16) * LDSB + cb);
                bb[ntt * 2][0]     = r[0];
                bb[ntt * 2 + 1][0] = r[1];
                bb[ntt * 2][1]     = r[2];
                bb[ntt * 2 + 1][1] = r[3];
            }
#pragma unroll
            for (int mt = 0; mt < 4; mt++)
#pragma unroll
                for (int nt = 0; nt < 4; nt++)
                    mma_fp16(acc[mt][nt], ah[mt], bb[nt]);
        }
        __syncthreads();
    }

    // ---------------- epilogue ----------------
    const int mbase = rowA0 + wm * 64;
    const int nbase = colB0 + wn * 32;
    const int lr = lane >> 2, lc = lane & 3;
    const long long zC = z * sC;

#pragma unroll
    for (int mt = 0; mt < 4; mt++) {
        const int m0 = mbase + mt * 16 + lr;
#pragma unroll
        for (int nt = 0; nt < 4; nt++) {
            const int n = nbase + nt * 8 + lc * 2;
            float b0 = 0.f, b1 = 0.f;
            if (HAS_BIAS) { b0 = bias[n]; b1 = bias[n + 1]; }
            float v0 = acc[mt][nt][0] * alpha + b0;
            float v1 = acc[mt][nt][1] * alpha + b1;
            float v2 = acc[mt][nt][2] * alpha + b0;
            float v3 = acc[mt][nt][3] * alpha + b1;
            if (OUT_MODE == 0) {
                *(float2*)&Cf[zC + (long long)m0 * N + n]       = make_float2(v0, v1);
                *(float2*)&Cf[zC + (long long)(m0 + 8) * N + n] = make_float2(v2, v3);
            } else if (OUT_MODE == 2) {
                *(uint32_t*)&Chi[zC + (long long)m0 * N + n]       = pk_f16x2(v0, v1);
                *(uint32_t*)&Chi[zC + (long long)(m0 + 8) * N + n] = pk_f16x2(v2, v3);
            } else {
                uint32_t h0 = pk_f16x2(v0, v1);
                uint32_t h1 = pk_f16x2(v2, v3);
                float2 r0 = resid2(v0, v1, h0);
                float2 r1 = resid2(v2, v3, h1);
                *(uint32_t*)&Chi[zC + (long long)m0 * N + n]       = h0;
                *(uint32_t*)&Chi[zC + (long long)(m0 + 8) * N + n] = h1;
                *(uint32_t*)&Clo[zC + (long long)m0 * N + n]       = pk_f16x2(r0.x, r0.y);
                *(uint32_t*)&Clo[zC + (long long)(m0 + 8) * N + n] = pk_f16x2(r1.x, r1.y);
            }
        }
    }
}

// ---------------- softmax + round (rows of 2048) ----------------
__global__ void __launch_bounds__(256) softmax_cvt(
    const float* __restrict__ S, __half* __restrict__ Sh)
{
    const long long row = blockIdx.x;
    const float* p = S + row * (long long)SEQ;
    const int tid = threadIdx.x;

    float4 v0 = *(const float4*)&p[tid * 4];
    float4 v1 = *(const float4*)&p[1024 + tid * 4];

    float m = fmaxf(fmaxf(fmaxf(v0.x, v0.y), fmaxf(v0.z, v0.w)),
                    fmaxf(fmaxf(v1.x, v1.y), fmaxf(v1.z, v1.w)));
    __shared__ float sh[8];
#pragma unroll
    for (int o = 16; o; o >>= 1) m = fmaxf(m, __shfl_xor_sync(0xffffffffu, m, o));
    if ((tid & 31) == 0) sh[tid >> 5] = m;
    __syncthreads();
    m = sh[0];
#pragma unroll
    for (int i = 1; i < 8; i++) m = fmaxf(m, sh[i]);
    __syncthreads();

    v0.x = __expf(v0.x - m); v0.y = __expf(v0.y - m);
    v0.z = __expf(v0.z - m); v0.w = __expf(v0.w - m);
    v1.x = __expf(v1.x - m); v1.y = __expf(v1.y - m);
    v1.z = __expf(v1.z - m); v1.w = __expf(v1.w - m);

    float s = (v0.x + v0.y + v0.z + v0.w) + (v1.x + v1.y + v1.z + v1.w);
#pragma unroll
    for (int o = 16; o; o >>= 1) s += __shfl_xor_sync(0xffffffffu, s, o);
    if ((tid & 31) == 0) sh[tid >> 5] = s;
    __syncthreads();
    s = 0.f;
#pragma unroll
    for (int i = 0; i < 8; i++) s += sh[i];

    const float inv = 1.f / s;
    v0.x *= inv; v0.y *= inv; v0.z *= inv; v0.w *= inv;
    v1.x *= inv; v1.y *= inv; v1.z *= inv; v1.w *= inv;

    const long long u0 = row * (SEQ / 2) + tid * 2;
    const long long u1 = u0 + 512;
    ((uint32_t*)Sh)[u0]     = pk_f16x2(v0.x, v0.y);
    ((uint32_t*)Sh)[u0 + 1] = pk_f16x2(v0.z, v0.w);
    ((uint32_t*)Sh)[u1]     = pk_f16x2(v1.x, v1.y);
    ((uint32_t*)Sh)[u1 + 1] = pk_f16x2(v1.z, v1.w);
}

// ---------------- V transpose (fp16 [SEQ,DM] -> fp16 [DM,SEQ]) ------------
__global__ void __launch_bounds__(256) transpose_h(
    const __half* __restrict__ V, __half* __restrict__ VT)
{
    __shared__ __half t[32][34];
    const long long z = blockIdx.z;
    const __half* Vb = V + z * (long long)SEQ * DM;
    __half* Hb = VT + z * (long long)DM * SEQ;
    const int d0 = blockIdx.x * 32;
    const int s0 = blockIdx.y * 32;
    const int tx = threadIdx.x, ty = threadIdx.y;
#pragma unroll
    for (int i = 0; i < 32; i += 8)
        t[ty + i][tx] = Vb[(long long)(s0 + ty + i) * DM + d0 + tx];
    __syncthreads();
#pragma unroll
    for (int i = 0; i < 32; i += 8)
        Hb[(long long)(d0 + ty + i) * SEQ + s0 + tx] = t[tx][ty + i];
}

// ---------------- host ----------------
extern "C" void kernel_launch(void* const* d_in, const int* in_sizes, int n_in,
                              void* d_out, int out_size)
{
    const float* x  = (const float*)d_in[0];
    const float* Wq = (const float*)d_in[1];
    const float* bq = (const float*)d_in[2];
    const float* Wk = (const float*)d_in[3];
    const float* bk = (const float*)d_in[4];
    const float* Wv = (const float*)d_in[5];
    const float* bv = (const float*)d_in[6];
    const float* Wo = (const float*)d_in[7];
    const float* bo = (const float*)d_in[8];
    float* out = (float*)d_out;

    float* Sf;
    __half *xh, *xl, *Wh, *Qh, *Kh, *Vh, *VTh, *Sh, *Aoh, *Aol;
    cudaGetSymbolAddress((void**)&Sf,  g_Sf);
    cudaGetSymbolAddress((void**)&xh,  g_xh);
    cudaGetSymbolAddress((void**)&xl,  g_xl);
    cudaGetSymbolAddress((void**)&Wh,  g_Wh);
    cudaGetSymbolAddress((void**)&Qh,  g_Qh);
    cudaGetSymbolAddress((void**)&Kh,  g_Kh);
    cudaGetSymbolAddress((void**)&Vh,  g_Vh);
    cudaGetSymbolAddress((void**)&VTh, g_VTh);
    cudaGetSymbolAddress((void**)&Sh,  g_Sh);
    cudaGetSymbolAddress((void**)&Aoh, g_Aoh);
    cudaGetSymbolAddress((void**)&Aol, g_Aol);

    cudaFuncSetAttribute(mma_gemm<2, 2, true>,
                         cudaFuncAttributeMaxDynamicSharedMemorySize, SMEM_BYTES);
    cudaFuncSetAttribute(mma_gemm<1, 0, false>,
                         cudaFuncAttributeMaxDynamicSharedMemorySize, SMEM_BYTES);
    cudaFuncSetAttribute(mma_gemm<1, 1, false>,
                         cudaFuncAttributeMaxDynamicSharedMemorySize, SMEM_BYTES);
    cudaFuncSetAttribute(mma_gemm<2, 0, true>,
                         cudaFuncAttributeMaxDynamicSharedMemorySize, SMEM_BYTES);

    const int nx4 = TOK * DM / 4;
    const int nw4 = DM * DM / 4;
    convert_split<<<(nx4 + 255) / 256, 256>>>(x, xh, xl, nx4);
    convert_round<<<(nw4 + 255) / 256, 256>>>(Wq, Wh + 0 * DM * DM, nw4);
    convert_round<<<(nw4 + 255) / 256, 256>>>(Wk, Wh + 1 * DM * DM, nw4);
    convert_round<<<(nw4 + 255) / 256, 256>>>(Wv, Wh + 2 * DM * DM, nw4);
    convert_round<<<(nw4 + 255) / 256, 256>>>(Wo, Wh + 3 * DM * DM, nw4);

    const dim3 blk(256);
    const dim3 gproj(DM / 128, TOK / 128, 1);        // (8, 64)
    const dim3 gscore(SEQ / 128, SEQ / 128, NB);     // (16, 16, 4)
    const dim3 gav(DM / 128, SEQ / 128, NB);         // (8, 16, 4)

    // projections: x split-2, output rounded fp16
    mma_gemm<2, 2, true><<<gproj, blk, SMEM_BYTES>>>(
        xh, xl, Wh + 0 * DM * DM, bq, nullptr, Qh, nullptr, DM, DM, 1.f, 0, 0, 0);
    mma_gemm<2, 2, true><<<gproj, blk, SMEM_BYTES>>>(
        xh, xl, Wh + 1 * DM * DM, bk, nullptr, Kh, nullptr, DM, DM, 1.f, 0, 0, 0);
    mma_gemm<2, 2, true><<<gproj, blk, SMEM_BYTES>>>(
        xh, xl, Wh + 2 * DM * DM, bv, nullptr, Vh, nullptr, DM, DM, 1.f, 0, 0, 0);

    transpose_h<<<dim3(DM / 32, SEQ / 32, NB), dim3(32, 8)>>>(Vh, VTh);

    // scores: single-phase, fp32 out
    mma_gemm<1, 0, false><<<gscore, blk, SMEM_BYTES>>>(
        Qh, nullptr, Kh, nullptr, Sf, nullptr, nullptr,
        SEQ, DM, 0.125f,
        (long long)SEQ * DM, (long long)SEQ * DM, (long long)SEQ * SEQ);

    softmax_cvt<<<TOK, blk>>>(Sf, Sh);

    // attn @ V: single-phase, hi/lo out (A-side of out-proj)
    mma_gemm<1, 1, false><<<gav, blk, SMEM_BYTES>>>(
        Sh, nullptr, VTh, nullptr, nullptr, Aoh, Aol,
        DM, SEQ, 1.f,
        (long long)SEQ * SEQ, (long long)DM * SEQ, (long long)SEQ * DM);

    // out proj: Ao split-2, fp32 out
    mma_gemm<2, 0, true><<<gproj, blk, SMEM_BYTES>>>(
        Aoh, Aol, Wh + 3 * DM * DM, bo, out, nullptr, nullptr, DM, DM, 1.f, 0, 0, 0);
}